// round 12
// baseline (speedup 1.0000x reference)
#include <cuda_runtime.h>
#include <cuda_bf16.h>
#include <math.h>
#include <cstdint>

#define B_ 64
#define H_ 1024

// ---------------------------------------------------------------------------
// Scratch (__device__ globals; allocation-free rule)
// ---------------------------------------------------------------------------
__device__ float g_s[9][B_ * H_];   // 9 pre-activations (fp32)
__device__ float g_ep[8][B_ * H_];  // split-K partials of e = k_t @ We
__device__ float4 g_gate[B_ * H_];  // (ft, it*vt, ot, nt) per row
__device__ float g_kb[B_ * H_];     // k_t + bk
__device__ float g_qb[B_ * H_];     // q_t + bq

// ---------------------------------------------------------------------------
// helpers
// ---------------------------------------------------------------------------
__device__ __forceinline__ uint32_t smem_u32(const void* p) {
    uint32_t a;
    asm("{ .reg .u64 t; cvta.to.shared.u64 t, %1; cvt.u32.u64 %0, t; }" : "=r"(a) : "l"(p));
    return a;
}

__device__ __forceinline__ void split2(float v0, float v1, uint32_t& hi, uint32_t& lo) {
    __nv_bfloat16 h0 = __float2bfloat16_rn(v0);
    __nv_bfloat16 h1 = __float2bfloat16_rn(v1);
    float l0 = v0 - __bfloat162float(h0);
    float l1 = v1 - __bfloat162float(h1);
    __nv_bfloat162 hp; hp.x = h0; hp.y = h1;
    __nv_bfloat162 lp = __floats2bfloat162_rn(l0, l1);
    hi = *(uint32_t*)&hp;
    lo = *(uint32_t*)&lp;
}

#define LDSM_X4(r0, r1, r2, r3, addr) \
    asm volatile("ldmatrix.sync.aligned.m8n8.x4.shared.b16 {%0,%1,%2,%3}, [%4];" \
        : "=r"(r0), "=r"(r1), "=r"(r2), "=r"(r3) : "r"(addr))
#define LDSM_X4T(r0, r1, r2, r3, addr) \
    asm volatile("ldmatrix.sync.aligned.m8n8.x4.trans.shared.b16 {%0,%1,%2,%3}, [%4];" \
        : "=r"(r0), "=r"(r1), "=r"(r2), "=r"(r3) : "r"(addr))
#define MMA16816(c, a0, a1, a2, a3, b0, b1) \
    asm volatile("mma.sync.aligned.m16n8k16.row.col.f32.bf16.bf16.f32 " \
        "{%0,%1,%2,%3}, {%4,%5,%6,%7}, {%8,%9}, {%0,%1,%2,%3};" \
        : "+f"(c[0]), "+f"(c[1]), "+f"(c[2]), "+f"(c[3]) \
        : "r"(a0), "r"(a1), "r"(a2), "r"(a3), "r"(b0), "r"(b1))

// ---------------------------------------------------------------------------
// Kernel 1: HALF-BATCH (M=32) HMMA bf16 3-term split GEMM. 9 jobs.
// grid (16 ntiles, 9 jobs), 256 threads (8 warps).
// Warp wid = (kh<<2)|(mw<<1)|nw : m16 (mw) x n32 (nw) x k512 (kh).
// ---------------------------------------------------------------------------
#define AROW 272
#define WROW 144
#define OFF_AH 0
#define OFF_AL 17408
#define OFF_WH 34816
#define OFF_WL 53248
#define STG    71680
#define SMEM_TOTAL (2 * STG)

__global__ __launch_bounds__(256, 1) void mma_half_kernel(
    int b0,
    const float* __restrict__ x, const float* __restrict__ h,
    const float* __restrict__ Wi, const float* __restrict__ Wf,
    const float* __restrict__ Wo, const float* __restrict__ Wk,
    const float* __restrict__ Wv, const float* __restrict__ Wq)
{
    extern __shared__ __align__(16) char smem[];
    const uint32_t sb = smem_u32(smem);
    const int tid = threadIdx.x;
    const int wid = tid >> 5;
    const int lane = tid & 31;
    const int job = blockIdx.y;
    const int n0 = blockIdx.x * 64;

    const float *A, *W;
    switch (job) {
        case 0: A = x; W = Wi;                          break;
        case 1: A = h; W = Wi + (size_t)1024 * 1024;    break;
        case 2: A = x; W = Wf;                          break;
        case 3: A = h; W = Wf + (size_t)1024 * 1024;    break;
        case 4: A = x; W = Wo;                          break;
        case 5: A = h; W = Wo + (size_t)1024 * 1024;    break;
        case 6: A = x; W = Wk;                          break;
        case 7: A = x; W = Wv;                          break;
        default: A = h; W = Wq;                         break;
    }
    A += (size_t)b0 * H_;
    float* out = g_s[job] + (size_t)b0 * H_;

    // ---- gmem load mapping: A 32x128 slab, W 128x64 slab per stage ----
    const int arow = tid >> 3;                   // 0..31 (m)
    const int acb  = (tid & 7) * 16;             // slab col base
    const int akg  = (acb & 63) + ((acb >= 64) ? 512 : 0);
    const int wrow = tid >> 1;                   // 0..127 (k in slab)
    const int wcb  = (tid & 1) * 32;
    const int wkg  = (wrow & 63) + ((wrow >= 64) ? 512 : 0);

    // ---- mma warp mapping ----
    const int kh = wid >> 2;
    const int mw = (wid >> 1) & 1;
    const int nw = wid & 1;
    const int m0 = mw * 16;
    const uint32_t a_off = (uint32_t)(m0 + (lane & 15)) * AROW
                         + (uint32_t)((lane >> 4) * 8 + kh * 64) * 2;
    const uint32_t b_off = (uint32_t)((lane & 7) + ((lane >> 3) & 1) * 8 + kh * 64) * WROW
                         + (uint32_t)((lane >> 4) * 8 + nw * 32) * 2;

    float acc[4][4] = {};   // [np*2 + hf][4]
    float4 pA[4], pW[8];

    #pragma unroll
    for (int j = 0; j < 4; j++)
        pA[j] = *(const float4*)(A + (size_t)arow * H_ + akg + j * 4);
    #pragma unroll
    for (int j = 0; j < 8; j++)
        pW[j] = *(const float4*)(W + (size_t)wkg * H_ + n0 + wcb + j * 4);
    {
        char* st = smem;
        #pragma unroll
        for (int j = 0; j < 4; j++) {
            uint32_t h0, l0, h1, l1;
            split2(pA[j].x, pA[j].y, h0, l0);
            split2(pA[j].z, pA[j].w, h1, l1);
            const uint32_t ao = (uint32_t)arow * AROW + (uint32_t)(acb + j * 4) * 2;
            *(uint2*)(st + OFF_AH + ao) = make_uint2(h0, h1);
            *(uint2*)(st + OFF_AL + ao) = make_uint2(l0, l1);
        }
        #pragma unroll
        for (int j = 0; j < 8; j++) {
            uint32_t h0, l0, h1, l1;
            split2(pW[j].x, pW[j].y, h0, l0);
            split2(pW[j].z, pW[j].w, h1, l1);
            const uint32_t wo = (uint32_t)wrow * WROW + (uint32_t)(wcb + j * 4) * 2;
            *(uint2*)(st + OFF_WH + wo) = make_uint2(h0, h1);
            *(uint2*)(st + OFF_WL + wo) = make_uint2(l0, l1);
        }
    }
    __syncthreads();

    #pragma unroll 1
    for (int t = 0; t < 8; t++) {
        const int s = t & 1;

        if (t < 7) {
            const int kc = (t + 1) * 64;
            #pragma unroll
            for (int j = 0; j < 4; j++)
                pA[j] = *(const float4*)(A + (size_t)arow * H_ + kc + akg + j * 4);
            #pragma unroll
            for (int j = 0; j < 8; j++)
                pW[j] = *(const float4*)(W + (size_t)(kc + wkg) * H_ + n0 + wcb + j * 4);
        }

        {
            const uint32_t ah = sb + s * STG + OFF_AH + a_off;
            const uint32_t al = sb + s * STG + OFF_AL + a_off;
            const uint32_t wh = sb + s * STG + OFF_WH + b_off;
            const uint32_t wl = sb + s * STG + OFF_WL + b_off;
            #pragma unroll
            for (int ks = 0; ks < 4; ks++) {
                const uint32_t ko2 = ks * 32;
                const uint32_t kor = ks * 16 * WROW;
                uint32_t ahr[4], alr[4];
                LDSM_X4(ahr[0], ahr[1], ahr[2], ahr[3], ah + ko2);
                LDSM_X4(alr[0], alr[1], alr[2], alr[3], al + ko2);
                #pragma unroll
                for (int np = 0; np < 2; np++) {
                    const uint32_t no = np * 32;
                    uint32_t b0r, b1r, b2r, b3r, f0, f1, f2, f3;
                    LDSM_X4T(b0r, b1r, b2r, b3r, wh + kor + no);
                    LDSM_X4T(f0, f1, f2, f3, wl + kor + no);
                    MMA16816(acc[np * 2],     ahr[0], ahr[1], ahr[2], ahr[3], b0r, b1r);
                    MMA16816(acc[np * 2],     ahr[0], ahr[1], ahr[2], ahr[3], f0, f1);
                    MMA16816(acc[np * 2],     alr[0], alr[1], alr[2], alr[3], b0r, b1r);
                    MMA16816(acc[np * 2 + 1], ahr[0], ahr[1], ahr[2], ahr[3], b2r, b3r);
                    MMA16816(acc[np * 2 + 1], ahr[0], ahr[1], ahr[2], ahr[3], f2, f3);
                    MMA16816(acc[np * 2 + 1], alr[0], alr[1], alr[2], alr[3], b2r, b3r);
                }
            }
        }

        if (t < 7) {
            char* st = smem + (s ^ 1) * STG;
            #pragma unroll
            for (int j = 0; j < 4; j++) {
                uint32_t h0, l0, h1, l1;
                split2(pA[j].x, pA[j].y, h0, l0);
                split2(pA[j].z, pA[j].w, h1, l1);
                const uint32_t ao = (uint32_t)arow * AROW + (uint32_t)(acb + j * 4) * 2;
                *(uint2*)(st + OFF_AH + ao) = make_uint2(h0, h1);
                *(uint2*)(st + OFF_AL + ao) = make_uint2(l0, l1);
            }
            #pragma unroll
            for (int j = 0; j < 8; j++) {
                uint32_t h0, l0, h1, l1;
                split2(pW[j].x, pW[j].y, h0, l0);
                split2(pW[j].z, pW[j].w, h1, l1);
                const uint32_t wo = (uint32_t)wrow * WROW + (uint32_t)(wcb + j * 4) * 2;
                *(uint2*)(st + OFF_WH + wo) = make_uint2(h0, h1);
                *(uint2*)(st + OFF_WL + wo) = make_uint2(l0, l1);
            }
        }
        __syncthreads();
    }

    // ---- cross-K-half reduction via smem (stride 20 floats) ----
    __syncthreads();
    float* red = (float*)smem;
    const int slot = ((mw * 2 + nw) * 32 + lane) * 20;
    if (kh == 1) {
        #pragma unroll
        for (int na = 0; na < 4; na++)
            *(float4*)(red + slot + na * 4) =
                make_float4(acc[na][0], acc[na][1], acc[na][2], acc[na][3]);
    }
    __syncthreads();
    if (kh == 0) {
        const int r0 = m0 + (lane >> 2);
        const int c0 = (lane & 3) * 2;
        #pragma unroll
        for (int np = 0; np < 2; np++) {
            #pragma unroll
            for (int hf = 0; hf < 2; hf++) {
                const int sI = np * 2 + hf;
                float4 o = *(const float4*)(red + slot + sI * 4);
                const int cg = n0 + nw * 32 + np * 16 + hf * 8 + c0;
                *(float2*)(out + (size_t)r0 * H_ + cg) =
                    make_float2(acc[sI][0] + o.x, acc[sI][1] + o.y);
                *(float2*)(out + (size_t)(r0 + 8) * H_ + cg) =
                    make_float2(acc[sI][2] + o.z, acc[sI][3] + o.w);
            }
        }
    }
}

// ---------------------------------------------------------------------------
// Kernel 2: e partials, HALF-BATCH (M=32). A = (g_s[6]+bk) rows b0..b0+31,
// W = We. split-K=8: grid (16 n-tiles, 8 k-chunks), 256 threads.
// ---------------------------------------------------------------------------
__global__ __launch_bounds__(256, 1) void egemm_half_kernel(
    int b0, const float* __restrict__ We, const float* __restrict__ bk)
{
    constexpr int TK = 32;
    __shared__ __align__(16) float As[2][TK][36];
    __shared__ __align__(16) float Ws[2][TK][68];

    const float* A0 = &g_s[6][0] + (size_t)b0 * H_;
    float* out = &g_ep[blockIdx.y][0] + (size_t)b0 * H_;
    const int kbase = blockIdx.y * 128;
    const int n0 = blockIdx.x * 64;
    const int t  = threadIdx.x;
    const int tr = t >> 4;          // 0..15 -> rows tr*2, tr*2+1
    const int tc = t & 15;          // cols tc*4

    const int arow = t >> 3;        // 0..31
    const int akq  = (t & 7) << 2;  // 0..28
    const int wr   = t >> 4;
    const int wc   = (t & 15) << 2;

    float acc[2][4] = {};
    float4 pa, pw0, pw1, pb;

    pa  = *(const float4*)(A0 + (size_t)arow * H_ + kbase + akq);
    pb  = *(const float4*)(bk + kbase + akq);
    pw0 = *(const float4*)(We + (size_t)(kbase + wr) * H_ + n0 + wc);
    pw1 = *(const float4*)(We + (size_t)(kbase + wr + 16) * H_ + n0 + wc);
    As[0][akq + 0][arow] = pa.x + pb.x;  As[0][akq + 1][arow] = pa.y + pb.y;
    As[0][akq + 2][arow] = pa.z + pb.z;  As[0][akq + 3][arow] = pa.w + pb.w;
    *(float4*)&Ws[0][wr][wc]      = pw0;
    *(float4*)&Ws[0][wr + 16][wc] = pw1;
    __syncthreads();

    #pragma unroll 1
    for (int tile = 0; tile < 4; tile++) {
        const int cur = tile & 1;
        const int nxt = cur ^ 1;
        if (tile + 1 < 4) {
            const int k0n = kbase + (tile + 1) * TK;
            pa  = *(const float4*)(A0 + (size_t)arow * H_ + k0n + akq);
            pb  = *(const float4*)(bk + k0n + akq);
            pw0 = *(const float4*)(We + (size_t)(k0n + wr) * H_ + n0 + wc);
            pw1 = *(const float4*)(We + (size_t)(k0n + wr + 16) * H_ + n0 + wc);
        }
        #pragma unroll
        for (int kk = 0; kk < TK; kk++) {
            const float a0 = As[cur][kk][tr * 2];
            const float a1 = As[cur][kk][tr * 2 + 1];
            float4 b = *(const float4*)&Ws[cur][kk][tc << 2];
            acc[0][0] = fmaf(a0, b.x, acc[0][0]);
            acc[0][1] = fmaf(a0, b.y, acc[0][1]);
            acc[0][2] = fmaf(a0, b.z, acc[0][2]);
            acc[0][3] = fmaf(a0, b.w, acc[0][3]);
            acc[1][0] = fmaf(a1, b.x, acc[1][0]);
            acc[1][1] = fmaf(a1, b.y, acc[1][1]);
            acc[1][2] = fmaf(a1, b.z, acc[1][2]);
            acc[1][3] = fmaf(a1, b.w, acc[1][3]);
        }
        if (tile + 1 < 4) {
            As[nxt][akq + 0][arow] = pa.x + pb.x;  As[nxt][akq + 1][arow] = pa.y + pb.y;
            As[nxt][akq + 2][arow] = pa.z + pb.z;  As[nxt][akq + 3][arow] = pa.w + pb.w;
            *(float4*)&Ws[nxt][wr][wc]      = pw0;
            *(float4*)&Ws[nxt][wr + 16][wc] = pw1;
        }
        __syncthreads();
    }

    #pragma unroll
    for (int i = 0; i < 2; i++) {
        int row = tr * 2 + i;
        float4 v = make_float4(acc[i][0], acc[i][1], acc[i][2], acc[i][3]);
        *(float4*)(out + (size_t)row * H_ + n0 + (tc << 2)) = v;
    }
}

// ---------------------------------------------------------------------------
// Kernel 2b: gates precompute, HALF-BATCH. grid 128 x 256 threads.
// ---------------------------------------------------------------------------
__device__ __forceinline__ float sigmoidf_(float z) {
    return 1.0f / (1.0f + expf(-z));
}

__global__ __launch_bounds__(256, 8) void gates_half_kernel(
    int b0, const float* __restrict__ n_prev,
    const float* __restrict__ bi, const float* __restrict__ bf,
    const float* __restrict__ bo, const float* __restrict__ bk,
    const float* __restrict__ bv, const float* __restrict__ bq,
    const float* __restrict__ be, float* __restrict__ out_n)
{
    const int br = b0 * H_ + blockIdx.x * 256 + threadIdx.x;
    const int r = br & (H_ - 1);

    const float it = sigmoidf_(g_s[0][br] + g_s[1][br] + bi[r]);
    const float ft = sigmoidf_(g_s[2][br] + g_s[3][br] + bf[r]);
    const float ot = sigmoidf_(g_s[4][br] + g_s[5][br] + bo[r]);
    const float vt = g_s[7][br] + bv[r];

    float e = be[r];
    #pragma unroll
    for (int p = 0; p < 8; p++) e += g_ep[p][br];
    const float nt = fmaf(ft, n_prev[br], it * expf(e));

    out_n[br] = nt;
    g_gate[br] = make_float4(ft, it * vt, ot, nt);
    g_kb[br] = g_s[6][br] + bk[r];
    g_qb[br] = g_s[8][br] + bq[r];
}

// ---------------------------------------------------------------------------
// Kernel 3: C-stream update, HALF-BATCH. grid (64 rowgroups, 32 batches).
// Row pair per warp; occupancy-tuned (R11-validated).
// ---------------------------------------------------------------------------
__global__ __launch_bounds__(256, 4) void update3_half_kernel(
    int b0, const float* __restrict__ C_prev,
    float* __restrict__ out_h, float* __restrict__ out_C)
{
    __shared__ __align__(16) float ks[H_];
    __shared__ __align__(16) float qs[H_];

    const int b    = b0 + blockIdx.y;
    const int tid  = threadIdx.x;
    const int wid  = tid >> 5;
    const int lane = tid & 31;

    {
        const int c = tid << 2;
        *(float4*)&ks[c] = *(const float4*)(&g_kb[b * H_] + c);
        *(float4*)&qs[c] = *(const float4*)(&g_qb[b * H_] + c);
    }
    __syncthreads();

    const int r0 = blockIdx.x * 16 + wid * 2;
    const int br0 = b * H_ + r0;
    const float4 g0 = g_gate[br0];
    const float4 g1 = g_gate[br0 + 1];
    const size_t base0 = (size_t)b * H_ * H_ + (size_t)r0 * H_;
    const size_t base1 = base0 + H_;

    float dA0 = 0.f, dB0 = 0.f, dA1 = 0.f, dB1 = 0.f;

    #pragma unroll 2
    for (int j = 0; j < 8; j++) {
        const int c = (lane << 2) + (j << 7);
        const float4 kv = *(const float4*)&ks[c];
        float4 cp0 = __ldcs((const float4*)(C_prev + base0 + c));
        float4 cp1 = __ldcs((const float4*)(C_prev + base1 + c));

        float4 ct0, ct1;
        ct0.x = fmaf(g0.x, cp0.x, g0.y * kv.x);
        ct0.y = fmaf(g0.x, cp0.y, g0.y * kv.y);
        ct0.z = fmaf(g0.x, cp0.z, g0.y * kv.z);
        ct0.w = fmaf(g0.x, cp0.w, g0.y * kv.w);
        ct1.x = fmaf(g1.x, cp1.x, g1.y * kv.x);
        ct1.y = fmaf(g1.x, cp1.y, g1.y * kv.y);
        ct1.z = fmaf(g1.x, cp1.z, g1.y * kv.z);
        ct1.w = fmaf(g1.x, cp1.w, g1.y * kv.w);
        __stcs((float4*)(out_C + base0 + c), ct0);
        __stcs((float4*)(out_C + base1 + c), ct1);

        const float4 qv = *(const float4*)&qs[c];
        dA0 = fmaf(ct0.x, qv.x, dA0);  dB0 = fmaf(ct0.y, qv.y, dB0);
        dA0 = fmaf(ct0.z, qv.z, dA0);  dB0 = fmaf(ct0.w, qv.w, dB0);
        dA1 = fmaf(ct1.x, qv.x, dA1);  dB1 = fmaf(ct1.y, qv.y, dB1);
        dA1 = fmaf(ct1.z, qv.z, dA1);  dB1 = fmaf(ct1.w, qv.w, dB1);
    }

    float dot0 = dA0 + dB0;
    float dot1 = dA1 + dB1;
    #pragma unroll
    for (int off = 16; off; off >>= 1) {
        dot0 += __shfl_xor_sync(0xffffffffu, dot0, off);
        dot1 += __shfl_xor_sync(0xffffffffu, dot1, off);
    }

    if (lane == 0) {
        out_h[br0]     = g0.z * dot0 / g0.w;
        out_h[br0 + 1] = g1.z * dot1 / g1.w;
    }
}

// ---------------------------------------------------------------------------
// Launch: two batch-halves, second half's GEMMs overlap first half's update
// via an event-forked non-blocking stream (graph-capture-legal fork/join).
// ---------------------------------------------------------------------------
extern "C" void kernel_launch(void* const* d_in, const int* in_sizes, int n_in,
                              void* d_out, int out_size)
{
    const float* x      = (const float*)d_in[0];
    const float* h_prev = (const float*)d_in[1];
    const float* C_prev = (const float*)d_in[2];
    const float* n_prev = (const float*)d_in[3];
    const float* Wi = (const float*)d_in[4];
    const float* bi = (const float*)d_in[5];
    const float* Wf = (const float*)d_in[6];
    const float* bf = (const float*)d_in[7];
    const float* Wo = (const float*)d_in[8];
    const float* bo = (const float*)d_in[9];
    const float* Wk = (const float*)d_in[10];
    const float* bk = (const float*)d_in[11];
    const float* Wv = (const float*)d_in[12];
    const float* bv = (const float*)d_in[13];
    const float* Wq = (const float*)d_in[14];
    const float* bq = (const float*)d_in[15];
    const float* We = (const float*)d_in[16];
    const float* be = (const float*)d_in[17];

    float* out_h = (float*)d_out;
    float* out_C = out_h + B_ * H_;
    float* out_n = out_C + (size_t)B_ * H_ * H_;

    static cudaStream_t s1 = nullptr;
    static cudaEvent_t evA = nullptr, evB = nullptr, evC = nullptr;
    if (!s1) {
        cudaStreamCreateWithFlags(&s1, cudaStreamNonBlocking);
        cudaEventCreateWithFlags(&evA, cudaEventDisableTiming);
        cudaEventCreateWithFlags(&evB, cudaEventDisableTiming);
        cudaEventCreateWithFlags(&evC, cudaEventDisableTiming);
        cudaFuncSetAttribute(mma_half_kernel,
                             cudaFuncAttributeMaxDynamicSharedMemorySize, SMEM_TOTAL);
    }

    // ---- half 0 GEMM chain (default stream) ----
    mma_half_kernel<<<dim3(16, 9), 256, SMEM_TOTAL>>>(0, x, h_prev, Wi, Wf, Wo, Wk, Wv, Wq);
    egemm_half_kernel<<<dim3(16, 8), 256>>>(0, We, bk);
    gates_half_kernel<<<128, 256>>>(0, n_prev, bi, bf, bo, bk, bv, bq, be, out_n);
    cudaEventRecord(evA, 0);

    // ---- fork: update half 0 on s1, overlapping half 1 GEMMs ----
    cudaStreamWaitEvent(s1, evA, 0);
    update3_half_kernel<<<dim3(64, 32), 256, 0, s1>>>(0, C_prev, out_h, out_C);

    // ---- half 1 GEMM chain (default stream, concurrent with update half 0) ----
    mma_half_kernel<<<dim3(16, 9), 256, SMEM_TOTAL>>>(32, x, h_prev, Wi, Wf, Wo, Wk, Wv, Wq);
    egemm_half_kernel<<<dim3(16, 8), 256>>>(32, We, bk);
    gates_half_kernel<<<128, 256>>>(32, n_prev, bi, bf, bo, bk, bv, bq, be, out_n);
    cudaEventRecord(evB, 0);

    // ---- update half 1 on s1 (after its GEMMs and after update half 0) ----
    cudaStreamWaitEvent(s1, evB, 0);
    update3_half_kernel<<<dim3(64, 32), 256, 0, s1>>>(32, C_prev, out_h, out_C);

    // ---- join s1 back into the capture origin stream ----
    cudaEventRecord(evC, s1);
    cudaStreamWaitEvent(0, evC, 0);
}

// round 14
// speedup vs baseline: 1.2758x; 1.2758x over previous
#include <cuda_runtime.h>
#include <cuda_bf16.h>
#include <math.h>
#include <cstdint>

#define B_ 64
#define H_ 1024

// ---------------------------------------------------------------------------
// Scratch (__device__ globals; allocation-free rule)
// ---------------------------------------------------------------------------
__device__ float g_s[9][B_ * H_];   // 9 pre-activations (fp32)
__device__ float g_ep[8][B_ * H_];  // split-K partials of e = k_t @ We
__device__ float4 g_gate[B_ * H_];  // (ft, it*vt, ot, nt) per row
__device__ float g_kb[B_ * H_];     // k_t + bk
__device__ float g_qb[B_ * H_];     // q_t + bq

// ---------------------------------------------------------------------------
// helpers
// ---------------------------------------------------------------------------
__device__ __forceinline__ uint32_t smem_u32(const void* p) {
    uint32_t a;
    asm("{ .reg .u64 t; cvta.to.shared.u64 t, %1; cvt.u32.u64 %0, t; }" : "=r"(a) : "l"(p));
    return a;
}

__device__ __forceinline__ void split2(float v0, float v1, uint32_t& hi, uint32_t& lo) {
    __nv_bfloat16 h0 = __float2bfloat16_rn(v0);
    __nv_bfloat16 h1 = __float2bfloat16_rn(v1);
    float l0 = v0 - __bfloat162float(h0);
    float l1 = v1 - __bfloat162float(h1);
    __nv_bfloat162 hp; hp.x = h0; hp.y = h1;
    __nv_bfloat162 lp = __floats2bfloat162_rn(l0, l1);
    hi = *(uint32_t*)&hp;
    lo = *(uint32_t*)&lp;
}

#define LDSM_X4(r0, r1, r2, r3, addr) \
    asm volatile("ldmatrix.sync.aligned.m8n8.x4.shared.b16 {%0,%1,%2,%3}, [%4];" \
        : "=r"(r0), "=r"(r1), "=r"(r2), "=r"(r3) : "r"(addr))
#define LDSM_X4T(r0, r1, r2, r3, addr) \
    asm volatile("ldmatrix.sync.aligned.m8n8.x4.trans.shared.b16 {%0,%1,%2,%3}, [%4];" \
        : "=r"(r0), "=r"(r1), "=r"(r2), "=r"(r3) : "r"(addr))
#define MMA16816(c, a0, a1, a2, a3, b0, b1) \
    asm volatile("mma.sync.aligned.m16n8k16.row.col.f32.bf16.bf16.f32 " \
        "{%0,%1,%2,%3}, {%4,%5,%6,%7}, {%8,%9}, {%0,%1,%2,%3};" \
        : "+f"(c[0]), "+f"(c[1]), "+f"(c[2]), "+f"(c[3]) \
        : "r"(a0), "r"(a1), "r"(a2), "r"(a3), "r"(b0), "r"(b1))

// ---------------------------------------------------------------------------
// Kernel 1: 9 GEMM jobs, HMMA bf16 3-term split. M=64, N=64/CTA, K=1024.
// grid (16 ntiles, 9 jobs), 256 threads (8 warps).
// Stage = k64 slab -> smem 2x36.9KB = 73.7KB -> 2 CTAs/SM (occupancy fix).
// Warp wid = (kh<<2)|(mw<<1)|nw : m32 (mw) x n32 (nw) x k32-within-slab (kh).
// ---------------------------------------------------------------------------
#define AROW 144                    // bytes (72 bf16)
#define WROW 144
#define OFF_AH 0
#define OFF_AL 9216
#define OFF_WH 18432
#define OFF_WL 27648
#define STG    36864
#define SMEM_TOTAL (2 * STG)        // 73728 B

__global__ __launch_bounds__(256, 2) void mma_kernel(
    const float* __restrict__ x, const float* __restrict__ h,
    const float* __restrict__ Wi, const float* __restrict__ Wf,
    const float* __restrict__ Wo, const float* __restrict__ Wk,
    const float* __restrict__ Wv, const float* __restrict__ Wq)
{
    extern __shared__ __align__(16) char smem[];
    const uint32_t sb = smem_u32(smem);
    const int tid = threadIdx.x;
    const int wid = tid >> 5;
    const int lane = tid & 31;
    const int job = blockIdx.y;
    const int n0 = blockIdx.x * 64;

    const float *A, *W;
    switch (job) {
        case 0: A = x; W = Wi;                          break;
        case 1: A = h; W = Wi + (size_t)1024 * 1024;    break;
        case 2: A = x; W = Wf;                          break;
        case 3: A = h; W = Wf + (size_t)1024 * 1024;    break;
        case 4: A = x; W = Wo;                          break;
        case 5: A = h; W = Wo + (size_t)1024 * 1024;    break;
        case 6: A = x; W = Wk;                          break;
        case 7: A = x; W = Wv;                          break;
        default: A = h; W = Wq;                         break;
    }
    float* out = g_s[job];

    // ---- gmem load mapping: per stage A 64x64 fp32, W 64x64 fp32 ----
    const int arow = tid >> 2;             // 0..63 (m row)
    const int acb  = (tid & 3) * 16;       // k col base in slab (16 floats)
    const int wrow = tid >> 2;             // 0..63 (k row in slab)
    const int wcb  = (tid & 3) * 16;       // n col base

    // ---- mma warp mapping (2M x 2N x 2kh over k64 slab) ----
    const int kh = wid >> 2;
    const int mw = (wid >> 1) & 1;
    const int nw = wid & 1;
    const int m0 = mw * 32;
    const uint32_t a_off = (uint32_t)(m0 + (lane & 15)) * AROW
                         + (uint32_t)((lane >> 4) * 8 + kh * 32) * 2;
    const uint32_t b_off = (uint32_t)((lane & 7) + ((lane >> 3) & 1) * 8 + kh * 32) * WROW
                         + (uint32_t)((lane >> 4) * 8 + nw * 32) * 2;

    float acc[8][4] = {};   // [mt*4 + np*2 + hf][4]
    float4 pA[4], pW[4];

    // ---- prologue: stage 0 ----
    #pragma unroll
    for (int j = 0; j < 4; j++) {
        pA[j] = *(const float4*)(A + (size_t)arow * H_ + acb + j * 4);
        pW[j] = *(const float4*)(W + (size_t)wrow * H_ + n0 + wcb + j * 4);
    }
    {
        char* st = smem;
        #pragma unroll
        for (int j = 0; j < 4; j++) {
            uint32_t h0, l0, h1, l1;
            split2(pA[j].x, pA[j].y, h0, l0);
            split2(pA[j].z, pA[j].w, h1, l1);
            const uint32_t ao = (uint32_t)arow * AROW + (uint32_t)(acb + j * 4) * 2;
            *(uint2*)(st + OFF_AH + ao) = make_uint2(h0, h1);
            *(uint2*)(st + OFF_AL + ao) = make_uint2(l0, l1);
            split2(pW[j].x, pW[j].y, h0, l0);
            split2(pW[j].z, pW[j].w, h1, l1);
            const uint32_t wo = (uint32_t)wrow * WROW + (uint32_t)(wcb + j * 4) * 2;
            *(uint2*)(st + OFF_WH + wo) = make_uint2(h0, h1);
            *(uint2*)(st + OFF_WL + wo) = make_uint2(l0, l1);
        }
    }
    __syncthreads();

    #pragma unroll 1
    for (int t = 0; t < 16; t++) {
        const int s = t & 1;

        // prefetch next k64 slab
        if (t < 15) {
            const int kc = (t + 1) * 64;
            #pragma unroll
            for (int j = 0; j < 4; j++) {
                pA[j] = *(const float4*)(A + (size_t)arow * H_ + kc + acb + j * 4);
                pW[j] = *(const float4*)(W + (size_t)(kc + wrow) * H_ + n0 + wcb + j * 4);
            }
        }

        // compute on stage s (this warp's k32 half of the slab)
        {
            const uint32_t ah = sb + s * STG + OFF_AH + a_off;
            const uint32_t al = sb + s * STG + OFF_AL + a_off;
            const uint32_t wh = sb + s * STG + OFF_WH + b_off;
            const uint32_t wl = sb + s * STG + OFF_WL + b_off;
            #pragma unroll
            for (int ks = 0; ks < 2; ks++) {
                const uint32_t ko2 = ks * 32;          // k16 step = 32 B
                const uint32_t kor = ks * 16 * WROW;
                uint32_t a0h[4], a0l[4], a1h[4], a1l[4];
                LDSM_X4(a0h[0], a0h[1], a0h[2], a0h[3], ah + ko2);
                LDSM_X4(a0l[0], a0l[1], a0l[2], a0l[3], al + ko2);
                LDSM_X4(a1h[0], a1h[1], a1h[2], a1h[3], ah + 16 * AROW + ko2);
                LDSM_X4(a1l[0], a1l[1], a1l[2], a1l[3], al + 16 * AROW + ko2);
                #pragma unroll
                for (int np = 0; np < 2; np++) {
                    const uint32_t no = np * 32;
                    uint32_t b0, b1, b2, b3, f0, f1, f2, f3;
                    LDSM_X4T(b0, b1, b2, b3, wh + kor + no);
                    LDSM_X4T(f0, f1, f2, f3, wl + kor + no);
                    // m-tile 0
                    MMA16816(acc[np * 2],     a0h[0], a0h[1], a0h[2], a0h[3], b0, b1);
                    MMA16816(acc[np * 2],     a0h[0], a0h[1], a0h[2], a0h[3], f0, f1);
                    MMA16816(acc[np * 2],     a0l[0], a0l[1], a0l[2], a0l[3], b0, b1);
                    MMA16816(acc[np * 2 + 1], a0h[0], a0h[1], a0h[2], a0h[3], b2, b3);
                    MMA16816(acc[np * 2 + 1], a0h[0], a0h[1], a0h[2], a0h[3], f2, f3);
                    MMA16816(acc[np * 2 + 1], a0l[0], a0l[1], a0l[2], a0l[3], b2, b3);
                    // m-tile 1
                    MMA16816(acc[4 + np * 2],     a1h[0], a1h[1], a1h[2], a1h[3], b0, b1);
                    MMA16816(acc[4 + np * 2],     a1h[0], a1h[1], a1h[2], a1h[3], f0, f1);
                    MMA16816(acc[4 + np * 2],     a1l[0], a1l[1], a1l[2], a1l[3], b0, b1);
                    MMA16816(acc[4 + np * 2 + 1], a1h[0], a1h[1], a1h[2], a1h[3], b2, b3);
                    MMA16816(acc[4 + np * 2 + 1], a1h[0], a1h[1], a1h[2], a1h[3], f2, f3);
                    MMA16816(acc[4 + np * 2 + 1], a1l[0], a1l[1], a1l[2], a1l[3], b2, b3);
                }
            }
        }

        // convert + store next slab into the other stage
        if (t < 15) {
            char* st = smem + (s ^ 1) * STG;
            #pragma unroll
            for (int j = 0; j < 4; j++) {
                uint32_t h0, l0, h1, l1;
                split2(pA[j].x, pA[j].y, h0, l0);
                split2(pA[j].z, pA[j].w, h1, l1);
                const uint32_t ao = (uint32_t)arow * AROW + (uint32_t)(acb + j * 4) * 2;
                *(uint2*)(st + OFF_AH + ao) = make_uint2(h0, h1);
                *(uint2*)(st + OFF_AL + ao) = make_uint2(l0, l1);
                split2(pW[j].x, pW[j].y, h0, l0);
                split2(pW[j].z, pW[j].w, h1, l1);
                const uint32_t wo = (uint32_t)wrow * WROW + (uint32_t)(wcb + j * 4) * 2;
                *(uint2*)(st + OFF_WH + wo) = make_uint2(h0, h1);
                *(uint2*)(st + OFF_WL + wo) = make_uint2(l0, l1);
            }
        }
        __syncthreads();
    }

    // ---- cross-K-half reduction via smem (R11-validated layout) ----
    __syncthreads();
    float* red = (float*)smem;
    const int slot = ((mw * 2 + nw) * 32 + lane) * 36;
    if (kh == 1) {
        #pragma unroll
        for (int na = 0; na < 8; na++)
            *(float4*)(red + slot + na * 4) =
                make_float4(acc[na][0], acc[na][1], acc[na][2], acc[na][3]);
    }
    __syncthreads();
    if (kh == 0) {
        const int r0 = m0 + (lane >> 2);
        const int c0 = (lane & 3) * 2;
        #pragma unroll
        for (int mt = 0; mt < 2; mt++) {
            #pragma unroll
            for (int np = 0; np < 2; np++) {
                #pragma unroll
                for (int hf = 0; hf < 2; hf++) {
                    const int sI = mt * 4 + np * 2 + hf;
                    float4 o = *(const float4*)(red + slot + sI * 4);
                    const int cg = n0 + nw * 32 + np * 16 + hf * 8 + c0;
                    const int rg = r0 + mt * 16;
                    *(float2*)(out + (size_t)rg * H_ + cg) =
                        make_float2(acc[sI][0] + o.x, acc[sI][1] + o.y);
                    *(float2*)(out + (size_t)(rg + 8) * H_ + cg) =
                        make_float2(acc[sI][2] + o.z, acc[sI][3] + o.w);
                }
            }
        }
    }
}

// ---------------------------------------------------------------------------
// Kernel 2: e partials. A = (g_s[6] + bk), W = We. split-K=8.
// ---------------------------------------------------------------------------
__global__ __launch_bounds__(256, 1) void egemm_kernel(
    const float* __restrict__ We, const float* __restrict__ bk)
{
    constexpr int TK = 32;
    __shared__ __align__(16) float As[2][TK][64 + 4];
    __shared__ __align__(16) float Ws[2][TK][64 + 4];

    const float* A0 = &g_s[6][0];
    float* out = &g_ep[blockIdx.y][0];
    const int kbase = blockIdx.y * 128;
    const int n0 = blockIdx.x * 64;
    const int t  = threadIdx.x;
    const int tr = t >> 4;
    const int tc = t & 15;

    const int arow = t >> 3;
    const int akq  = (t & 7) << 2;
    const int wr   = t >> 4;
    const int wc   = (t & 15) << 2;

    float acc[4][4] = {};
    float4 pa0, pa1, pw0, pw1, pb;

    pa0 = *(const float4*)(A0 + arow * H_ + kbase + akq);
    pa1 = *(const float4*)(A0 + (arow + 32) * H_ + kbase + akq);
    pb  = *(const float4*)(bk + kbase + akq);
    pw0 = *(const float4*)(We + (size_t)(kbase + wr) * H_ + n0 + wc);
    pw1 = *(const float4*)(We + (size_t)(kbase + wr + 16) * H_ + n0 + wc);
    As[0][akq + 0][arow] = pa0.x + pb.x;  As[0][akq + 1][arow] = pa0.y + pb.y;
    As[0][akq + 2][arow] = pa0.z + pb.z;  As[0][akq + 3][arow] = pa0.w + pb.w;
    As[0][akq + 0][arow + 32] = pa1.x + pb.x;  As[0][akq + 1][arow + 32] = pa1.y + pb.y;
    As[0][akq + 2][arow + 32] = pa1.z + pb.z;  As[0][akq + 3][arow + 32] = pa1.w + pb.w;
    *(float4*)&Ws[0][wr][wc]      = pw0;
    *(float4*)&Ws[0][wr + 16][wc] = pw1;
    __syncthreads();

    #pragma unroll 1
    for (int tile = 0; tile < 4; tile++) {
        const int cur = tile & 1;
        const int nxt = cur ^ 1;
        if (tile + 1 < 4) {
            const int k0n = kbase + (tile + 1) * TK;
            pa0 = *(const float4*)(A0 + arow * H_ + k0n + akq);
            pa1 = *(const float4*)(A0 + (arow + 32) * H_ + k0n + akq);
            pb  = *(const float4*)(bk + k0n + akq);
            pw0 = *(const float4*)(We + (size_t)(k0n + wr) * H_ + n0 + wc);
            pw1 = *(const float4*)(We + (size_t)(k0n + wr + 16) * H_ + n0 + wc);
        }
        #pragma unroll
        for (int kk = 0; kk < TK; kk++) {
            float4 a = *(const float4*)&As[cur][kk][tr << 2];
            float4 b = *(const float4*)&Ws[cur][kk][tc << 2];
            #pragma unroll
            for (int i = 0; i < 4; i++) {
                float av = (i == 0) ? a.x : (i == 1) ? a.y : (i == 2) ? a.z : a.w;
                acc[i][0] = fmaf(av, b.x, acc[i][0]);
                acc[i][1] = fmaf(av, b.y, acc[i][1]);
                acc[i][2] = fmaf(av, b.z, acc[i][2]);
                acc[i][3] = fmaf(av, b.w, acc[i][3]);
            }
        }
        if (tile + 1 < 4) {
            As[nxt][akq + 0][arow] = pa0.x + pb.x;  As[nxt][akq + 1][arow] = pa0.y + pb.y;
            As[nxt][akq + 2][arow] = pa0.z + pb.z;  As[nxt][akq + 3][arow] = pa0.w + pb.w;
            As[nxt][akq + 0][arow + 32] = pa1.x + pb.x;  As[nxt][akq + 1][arow + 32] = pa1.y + pb.y;
            As[nxt][akq + 2][arow + 32] = pa1.z + pb.z;  As[nxt][akq + 3][arow + 32] = pa1.w + pb.w;
            *(float4*)&Ws[nxt][wr][wc]      = pw0;
            *(float4*)&Ws[nxt][wr + 16][wc] = pw1;
        }
        __syncthreads();
    }

    #pragma unroll
    for (int i = 0; i < 4; i++) {
        int row = (tr << 2) + i;
        float4 v = make_float4(acc[i][0], acc[i][1], acc[i][2], acc[i][3]);
        *(float4*)(out + row * H_ + n0 + (tc << 2)) = v;
    }
}

// ---------------------------------------------------------------------------
// Kernel 2b: gates precompute
// ---------------------------------------------------------------------------
__device__ __forceinline__ float sigmoidf_(float z) {
    return 1.0f / (1.0f + expf(-z));
}

__global__ __launch_bounds__(256, 8) void gates_kernel(
    const float* __restrict__ n_prev,
    const float* __restrict__ bi, const float* __restrict__ bf,
    const float* __restrict__ bo, const float* __restrict__ bk,
    const float* __restrict__ bv, const float* __restrict__ bq,
    const float* __restrict__ be, float* __restrict__ out_n)
{
    const int br = blockIdx.x * 256 + threadIdx.x;
    const int r = br & (H_ - 1);

    const float it = sigmoidf_(g_s[0][br] + g_s[1][br] + bi[r]);
    const float ft = sigmoidf_(g_s[2][br] + g_s[3][br] + bf[r]);
    const float ot = sigmoidf_(g_s[4][br] + g_s[5][br] + bo[r]);
    const float vt = g_s[7][br] + bv[r];

    float e = be[r];
    #pragma unroll
    for (int p = 0; p < 8; p++) e += g_ep[p][br];
    const float nt = fmaf(ft, n_prev[br], it * expf(e));

    out_n[br] = nt;
    g_gate[br] = make_float4(ft, it * vt, ot, nt);
    g_kb[br] = g_s[6][br] + bk[r];
    g_qb[br] = g_s[8][br] + bq[r];
}

// ---------------------------------------------------------------------------
// Kernel 3: C-stream update v3b (R11-validated, 86.6us)
// ---------------------------------------------------------------------------
__global__ __launch_bounds__(256, 4) void update3_kernel(
    const float* __restrict__ C_prev,
    float* __restrict__ out_h, float* __restrict__ out_C)
{
    __shared__ __align__(16) float ks[H_];
    __shared__ __align__(16) float qs[H_];

    const int b    = blockIdx.y;
    const int tid  = threadIdx.x;
    const int wid  = tid >> 5;
    const int lane = tid & 31;

    {
        const int c = tid << 2;
        *(float4*)&ks[c] = *(const float4*)(&g_kb[b * H_] + c);
        *(float4*)&qs[c] = *(const float4*)(&g_qb[b * H_] + c);
    }
    __syncthreads();

    const int r0 = blockIdx.x * 16 + wid * 2;
    const int br0 = b * H_ + r0;
    const float4 g0 = g_gate[br0];
    const float4 g1 = g_gate[br0 + 1];
    const size_t base0 = (size_t)b * H_ * H_ + (size_t)r0 * H_;
    const size_t base1 = base0 + H_;

    float dA0 = 0.f, dB0 = 0.f, dA1 = 0.f, dB1 = 0.f;

    #pragma unroll 2
    for (int j = 0; j < 8; j++) {
        const int c = (lane << 2) + (j << 7);
        const float4 kv = *(const float4*)&ks[c];
        float4 cp0 = __ldcs((const float4*)(C_prev + base0 + c));
        float4 cp1 = __ldcs((const float4*)(C_prev + base1 + c));

        float4 ct0, ct1;
        ct0.x = fmaf(g0.x, cp0.x, g0.y * kv.x);
        ct0.y = fmaf(g0.x, cp0.y, g0.y * kv.y);
        ct0.z = fmaf(g0.x, cp0.z, g0.y * kv.z);
        ct0.w = fmaf(g0.x, cp0.w, g0.y * kv.w);
        ct1.x = fmaf(g1.x, cp1.x, g1.y * kv.x);
        ct1.y = fmaf(g1.x, cp1.y, g1.y * kv.y);
        ct1.z = fmaf(g1.x, cp1.z, g1.y * kv.z);
        ct1.w = fmaf(g1.x, cp1.w, g1.y * kv.w);
        __stcs((float4*)(out_C + base0 + c), ct0);
        __stcs((float4*)(out_C + base1 + c), ct1);

        const float4 qv = *(const float4*)&qs[c];
        dA0 = fmaf(ct0.x, qv.x, dA0);  dB0 = fmaf(ct0.y, qv.y, dB0);
        dA0 = fmaf(ct0.z, qv.z, dA0);  dB0 = fmaf(ct0.w, qv.w, dB0);
        dA1 = fmaf(ct1.x, qv.x, dA1);  dB1 = fmaf(ct1.y, qv.y, dB1);
        dA1 = fmaf(ct1.z, qv.z, dA1);  dB1 = fmaf(ct1.w, qv.w, dB1);
    }

    float dot0 = dA0 + dB0;
    float dot1 = dA1 + dB1;
    #pragma unroll
    for (int off = 16; off; off >>= 1) {
        dot0 += __shfl_xor_sync(0xffffffffu, dot0, off);
        dot1 += __shfl_xor_sync(0xffffffffu, dot1, off);
    }

    if (lane == 0) {
        out_h[br0]     = g0.z * dot0 / g0.w;
        out_h[br0 + 1] = g1.z * dot1 / g1.w;
    }
}

// ---------------------------------------------------------------------------
extern "C" void kernel_launch(void* const* d_in, const int* in_sizes, int n_in,
                              void* d_out, int out_size)
{
    const float* x      = (const float*)d_in[0];
    const float* h_prev = (const float*)d_in[1];
    const float* C_prev = (const float*)d_in[2];
    const float* n_prev = (const float*)d_in[3];
    const float* Wi = (const float*)d_in[4];
    const float* bi = (const float*)d_in[5];
    const float* Wf = (const float*)d_in[6];
    const float* bf = (const float*)d_in[7];
    const float* Wo = (const float*)d_in[8];
    const float* bo = (const float*)d_in[9];
    const float* Wk = (const float*)d_in[10];
    const float* bk = (const float*)d_in[11];
    const float* Wv = (const float*)d_in[12];
    const float* bv = (const float*)d_in[13];
    const float* Wq = (const float*)d_in[14];
    const float* bq = (const float*)d_in[15];
    const float* We = (const float*)d_in[16];
    const float* be = (const float*)d_in[17];

    float* out_h = (float*)d_out;
    float* out_C = out_h + B_ * H_;
    float* out_n = out_C + (size_t)B_ * H_ * H_;

    static int smem_set = 0;
    if (!smem_set) {
        cudaFuncSetAttribute(mma_kernel, cudaFuncAttributeMaxDynamicSharedMemorySize,
                             SMEM_TOTAL);
        smem_set = 1;
    }

    mma_kernel<<<dim3(16, 9), 256, SMEM_TOTAL>>>(x, h_prev, Wi, Wf, Wo, Wk, Wv, Wq);
    egemm_kernel<<<dim3(16, 8), 256>>>(We, bk);
    gates_kernel<<<256, 256>>>(n_prev, bi, bf, bo, bk, bv, bq, be, out_n);
    update3_kernel<<<dim3(64, 64), 256>>>(C_prev, out_h, out_C);
}

// round 15
// speedup vs baseline: 1.3268x; 1.0400x over previous
#include <cuda_runtime.h>
#include <cuda_bf16.h>
#include <math.h>
#include <cstdint>

#define B_ 64
#define H_ 1024

// ---------------------------------------------------------------------------
// Scratch (__device__ globals; allocation-free rule)
// ---------------------------------------------------------------------------
__device__ float g_s2[18][B_ * H_]; // 18 split-K partial pre-activations
__device__ float g_ep[8][B_ * H_];  // split-K partials of e = k_t @ We
__device__ float4 g_gate[B_ * H_];  // (ft, it*vt, ot, nt) per row
__device__ float g_kb[B_ * H_];     // k_t + bk
__device__ float g_qb[B_ * H_];     // q_t + bq

// ---------------------------------------------------------------------------
// helpers
// ---------------------------------------------------------------------------
__device__ __forceinline__ uint32_t smem_u32(const void* p) {
    uint32_t a;
    asm("{ .reg .u64 t; cvta.to.shared.u64 t, %1; cvt.u32.u64 %0, t; }" : "=r"(a) : "l"(p));
    return a;
}

__device__ __forceinline__ void split2(float v0, float v1, uint32_t& hi, uint32_t& lo) {
    __nv_bfloat16 h0 = __float2bfloat16_rn(v0);
    __nv_bfloat16 h1 = __float2bfloat16_rn(v1);
    float l0 = v0 - __bfloat162float(h0);
    float l1 = v1 - __bfloat162float(h1);
    __nv_bfloat162 hp; hp.x = h0; hp.y = h1;
    __nv_bfloat162 lp = __floats2bfloat162_rn(l0, l1);
    hi = *(uint32_t*)&hp;
    lo = *(uint32_t*)&lp;
}

#define LDSM_X4(r0, r1, r2, r3, addr) \
    asm volatile("ldmatrix.sync.aligned.m8n8.x4.shared.b16 {%0,%1,%2,%3}, [%4];" \
        : "=r"(r0), "=r"(r1), "=r"(r2), "=r"(r3) : "r"(addr))
#define LDSM_X4T(r0, r1, r2, r3, addr) \
    asm volatile("ldmatrix.sync.aligned.m8n8.x4.trans.shared.b16 {%0,%1,%2,%3}, [%4];" \
        : "=r"(r0), "=r"(r1), "=r"(r2), "=r"(r3) : "r"(addr))
#define MMA16816(c, a0, a1, a2, a3, b0, b1) \
    asm volatile("mma.sync.aligned.m16n8k16.row.col.f32.bf16.bf16.f32 " \
        "{%0,%1,%2,%3}, {%4,%5,%6,%7}, {%8,%9}, {%0,%1,%2,%3};" \
        : "+f"(c[0]), "+f"(c[1]), "+f"(c[2]), "+f"(c[3]) \
        : "r"(a0), "r"(a1), "r"(a2), "r"(a3), "r"(b0), "r"(b1))

// ---------------------------------------------------------------------------
// Kernel 1: 18 split-K partial GEMMs (9 jobs x K-half 512), HMMA bf16 3-term.
// M=64, N=64/CTA, K=512/CTA. grid (16 ntiles, 18) = 288 CTAs -> 2 CTAs/SM.
// Stage = k64 slab (NT=8). Warp wid = (kh<<2)|(mw<<1)|nw.
// ---------------------------------------------------------------------------
#define AROW 144                    // bytes (72 bf16)
#define WROW 144
#define OFF_AH 0
#define OFF_AL 9216
#define OFF_WH 18432
#define OFF_WL 27648
#define STG    36864
#define SMEM_TOTAL (2 * STG)        // 73728 B

__global__ __launch_bounds__(256, 2) void mma_kernel(
    const float* __restrict__ x, const float* __restrict__ h,
    const float* __restrict__ Wi, const float* __restrict__ Wf,
    const float* __restrict__ Wo, const float* __restrict__ Wk,
    const float* __restrict__ Wv, const float* __restrict__ Wq)
{
    extern __shared__ __align__(16) char smem[];
    const uint32_t sb = smem_u32(smem);
    const int tid = threadIdx.x;
    const int wid = tid >> 5;
    const int lane = tid & 31;
    const int job = blockIdx.y >> 1;       // 0..8
    const int ksp = blockIdx.y & 1;        // K-half 0/1
    const int n0 = blockIdx.x * 64;

    const float *A, *W;
    switch (job) {
        case 0: A = x; W = Wi;                          break;
        case 1: A = h; W = Wi + (size_t)1024 * 1024;    break;
        case 2: A = x; W = Wf;                          break;
        case 3: A = h; W = Wf + (size_t)1024 * 1024;    break;
        case 4: A = x; W = Wo;                          break;
        case 5: A = h; W = Wo + (size_t)1024 * 1024;    break;
        case 6: A = x; W = Wk;                          break;
        case 7: A = x; W = Wv;                          break;
        default: A = h; W = Wq;                         break;
    }
    A += ksp * 512;                        // column offset (row stride H_)
    W += (size_t)(ksp * 512) * H_;         // row offset
    float* out = g_s2[blockIdx.y];

    // ---- gmem load mapping: per stage A 64x64 fp32, W 64x64 fp32 ----
    const int arow = tid >> 2;             // 0..63 (m row)
    const int acb  = (tid & 3) * 16;       // k col base in slab
    const int wrow = tid >> 2;             // 0..63 (k row in slab)
    const int wcb  = (tid & 3) * 16;       // n col base

    // ---- mma warp mapping (2M x 2N x 2kh over k64 slab) ----
    const int kh = wid >> 2;
    const int mw = (wid >> 1) & 1;
    const int nw = wid & 1;
    const int m0 = mw * 32;
    const uint32_t a_off = (uint32_t)(m0 + (lane & 15)) * AROW
                         + (uint32_t)((lane >> 4) * 8 + kh * 32) * 2;
    const uint32_t b_off = (uint32_t)((lane & 7) + ((lane >> 3) & 1) * 8 + kh * 32) * WROW
                         + (uint32_t)((lane >> 4) * 8 + nw * 32) * 2;

    float acc[8][4] = {};   // [mt*4 + np*2 + hf][4]
    float4 pA[4], pW[4];

    // ---- prologue: stage 0 ----
    #pragma unroll
    for (int j = 0; j < 4; j++) {
        pA[j] = *(const float4*)(A + (size_t)arow * H_ + acb + j * 4);
        pW[j] = *(const float4*)(W + (size_t)wrow * H_ + n0 + wcb + j * 4);
    }
    {
        char* st = smem;
        #pragma unroll
        for (int j = 0; j < 4; j++) {
            uint32_t h0, l0, h1, l1;
            split2(pA[j].x, pA[j].y, h0, l0);
            split2(pA[j].z, pA[j].w, h1, l1);
            const uint32_t ao = (uint32_t)arow * AROW + (uint32_t)(acb + j * 4) * 2;
            *(uint2*)(st + OFF_AH + ao) = make_uint2(h0, h1);
            *(uint2*)(st + OFF_AL + ao) = make_uint2(l0, l1);
            split2(pW[j].x, pW[j].y, h0, l0);
            split2(pW[j].z, pW[j].w, h1, l1);
            const uint32_t wo = (uint32_t)wrow * WROW + (uint32_t)(wcb + j * 4) * 2;
            *(uint2*)(st + OFF_WH + wo) = make_uint2(h0, h1);
            *(uint2*)(st + OFF_WL + wo) = make_uint2(l0, l1);
        }
    }
    __syncthreads();

    #pragma unroll 1
    for (int t = 0; t < 8; t++) {
        const int s = t & 1;

        // prefetch next k64 slab
        if (t < 7) {
            const int kc = (t + 1) * 64;
            #pragma unroll
            for (int j = 0; j < 4; j++) {
                pA[j] = *(const float4*)(A + (size_t)arow * H_ + kc + acb + j * 4);
                pW[j] = *(const float4*)(W + (size_t)(kc + wrow) * H_ + n0 + wcb + j * 4);
            }
        }

        // compute on stage s (this warp's k32 half of the slab)
        {
            const uint32_t ah = sb + s * STG + OFF_AH + a_off;
            const uint32_t al = sb + s * STG + OFF_AL + a_off;
            const uint32_t wh = sb + s * STG + OFF_WH + b_off;
            const uint32_t wl = sb + s * STG + OFF_WL + b_off;
            #pragma unroll
            for (int ks = 0; ks < 2; ks++) {
                const uint32_t ko2 = ks * 32;
                const uint32_t kor = ks * 16 * WROW;
                uint32_t a0h[4], a0l[4], a1h[4], a1l[4];
                LDSM_X4(a0h[0], a0h[1], a0h[2], a0h[3], ah + ko2);
                LDSM_X4(a0l[0], a0l[1], a0l[2], a0l[3], al + ko2);
                LDSM_X4(a1h[0], a1h[1], a1h[2], a1h[3], ah + 16 * AROW + ko2);
                LDSM_X4(a1l[0], a1l[1], a1l[2], a1l[3], al + 16 * AROW + ko2);
                #pragma unroll
                for (int np = 0; np < 2; np++) {
                    const uint32_t no = np * 32;
                    uint32_t b0, b1, b2, b3, f0, f1, f2, f3;
                    LDSM_X4T(b0, b1, b2, b3, wh + kor + no);
                    LDSM_X4T(f0, f1, f2, f3, wl + kor + no);
                    // m-tile 0
                    MMA16816(acc[np * 2],     a0h[0], a0h[1], a0h[2], a0h[3], b0, b1);
                    MMA16816(acc[np * 2],     a0h[0], a0h[1], a0h[2], a0h[3], f0, f1);
                    MMA16816(acc[np * 2],     a0l[0], a0l[1], a0l[2], a0l[3], b0, b1);
                    MMA16816(acc[np * 2 + 1], a0h[0], a0h[1], a0h[2], a0h[3], b2, b3);
                    MMA16816(acc[np * 2 + 1], a0h[0], a0h[1], a0h[2], a0h[3], f2, f3);
                    MMA16816(acc[np * 2 + 1], a0l[0], a0l[1], a0l[2], a0l[3], b2, b3);
                    // m-tile 1
                    MMA16816(acc[4 + np * 2],     a1h[0], a1h[1], a1h[2], a1h[3], b0, b1);
                    MMA16816(acc[4 + np * 2],     a1h[0], a1h[1], a1h[2], a1h[3], f0, f1);
                    MMA16816(acc[4 + np * 2],     a1l[0], a1l[1], a1l[2], a1l[3], b0, b1);
                    MMA16816(acc[4 + np * 2 + 1], a1h[0], a1h[1], a1h[2], a1h[3], b2, b3);
                    MMA16816(acc[4 + np * 2 + 1], a1h[0], a1h[1], a1h[2], a1h[3], f2, f3);
                    MMA16816(acc[4 + np * 2 + 1], a1l[0], a1l[1], a1l[2], a1l[3], b2, b3);
                }
            }
        }

        // convert + store next slab into the other stage
        if (t < 7) {
            char* st = smem + (s ^ 1) * STG;
            #pragma unroll
            for (int j = 0; j < 4; j++) {
                uint32_t h0, l0, h1, l1;
                split2(pA[j].x, pA[j].y, h0, l0);
                split2(pA[j].z, pA[j].w, h1, l1);
                const uint32_t ao = (uint32_t)arow * AROW + (uint32_t)(acb + j * 4) * 2;
                *(uint2*)(st + OFF_AH + ao) = make_uint2(h0, h1);
                *(uint2*)(st + OFF_AL + ao) = make_uint2(l0, l1);
                split2(pW[j].x, pW[j].y, h0, l0);
                split2(pW[j].z, pW[j].w, h1, l1);
                const uint32_t wo = (uint32_t)wrow * WROW + (uint32_t)(wcb + j * 4) * 2;
                *(uint2*)(st + OFF_WH + wo) = make_uint2(h0, h1);
                *(uint2*)(st + OFF_WL + wo) = make_uint2(l0, l1);
            }
        }
        __syncthreads();
    }

    // ---- cross-K-half reduction via smem (R11-validated layout) ----
    __syncthreads();
    float* red = (float*)smem;
    const int slot = ((mw * 2 + nw) * 32 + lane) * 36;
    if (kh == 1) {
        #pragma unroll
        for (int na = 0; na < 8; na++)
            *(float4*)(red + slot + na * 4) =
                make_float4(acc[na][0], acc[na][1], acc[na][2], acc[na][3]);
    }
    __syncthreads();
    if (kh == 0) {
        const int r0 = m0 + (lane >> 2);
        const int c0 = (lane & 3) * 2;
        #pragma unroll
        for (int mt = 0; mt < 2; mt++) {
            #pragma unroll
            for (int np = 0; np < 2; np++) {
                #pragma unroll
                for (int hf = 0; hf < 2; hf++) {
                    const int sI = mt * 4 + np * 2 + hf;
                    float4 o = *(const float4*)(red + slot + sI * 4);
                    const int cg = n0 + nw * 32 + np * 16 + hf * 8 + c0;
                    const int rg = r0 + mt * 16;
                    *(float2*)(out + (size_t)rg * H_ + cg) =
                        make_float2(acc[sI][0] + o.x, acc[sI][1] + o.y);
                    *(float2*)(out + (size_t)(rg + 8) * H_ + cg) =
                        make_float2(acc[sI][2] + o.z, acc[sI][3] + o.w);
                }
            }
        }
    }
}

// ---------------------------------------------------------------------------
// Kernel 2: e partials. A = (g_s2[12]+g_s2[13] + bk), W = We. split-K=8.
// (pair-sum A-load pattern R3-validated)
// ---------------------------------------------------------------------------
__global__ __launch_bounds__(256, 1) void egemm_kernel(
    const float* __restrict__ We, const float* __restrict__ bk)
{
    constexpr int TK = 32;
    __shared__ __align__(16) float As[2][TK][64 + 4];
    __shared__ __align__(16) float Ws[2][TK][64 + 4];

    const float* A0 = &g_s2[12][0];
    const float* A1 = &g_s2[13][0];
    float* out = &g_ep[blockIdx.y][0];
    const int kbase = blockIdx.y * 128;
    const int n0 = blockIdx.x * 64;
    const int t  = threadIdx.x;
    const int tr = t >> 4;
    const int tc = t & 15;

    const int arow = t >> 3;
    const int akq  = (t & 7) << 2;
    const int wr   = t >> 4;
    const int wc   = (t & 15) << 2;

    float acc[4][4] = {};
    float4 pa0, pa1, pc0, pc1, pw0, pw1, pb;

    pa0 = *(const float4*)(A0 + arow * H_ + kbase + akq);
    pc0 = *(const float4*)(A1 + arow * H_ + kbase + akq);
    pa1 = *(const float4*)(A0 + (arow + 32) * H_ + kbase + akq);
    pc1 = *(const float4*)(A1 + (arow + 32) * H_ + kbase + akq);
    pb  = *(const float4*)(bk + kbase + akq);
    pw0 = *(const float4*)(We + (size_t)(kbase + wr) * H_ + n0 + wc);
    pw1 = *(const float4*)(We + (size_t)(kbase + wr + 16) * H_ + n0 + wc);
    As[0][akq + 0][arow] = pa0.x + pc0.x + pb.x;
    As[0][akq + 1][arow] = pa0.y + pc0.y + pb.y;
    As[0][akq + 2][arow] = pa0.z + pc0.z + pb.z;
    As[0][akq + 3][arow] = pa0.w + pc0.w + pb.w;
    As[0][akq + 0][arow + 32] = pa1.x + pc1.x + pb.x;
    As[0][akq + 1][arow + 32] = pa1.y + pc1.y + pb.y;
    As[0][akq + 2][arow + 32] = pa1.z + pc1.z + pb.z;
    As[0][akq + 3][arow + 32] = pa1.w + pc1.w + pb.w;
    *(float4*)&Ws[0][wr][wc]      = pw0;
    *(float4*)&Ws[0][wr + 16][wc] = pw1;
    __syncthreads();

    #pragma unroll 1
    for (int tile = 0; tile < 4; tile++) {
        const int cur = tile & 1;
        const int nxt = cur ^ 1;
        if (tile + 1 < 4) {
            const int k0n = kbase + (tile + 1) * TK;
            pa0 = *(const float4*)(A0 + arow * H_ + k0n + akq);
            pc0 = *(const float4*)(A1 + arow * H_ + k0n + akq);
            pa1 = *(const float4*)(A0 + (arow + 32) * H_ + k0n + akq);
            pc1 = *(const float4*)(A1 + (arow + 32) * H_ + k0n + akq);
            pb  = *(const float4*)(bk + k0n + akq);
            pw0 = *(const float4*)(We + (size_t)(k0n + wr) * H_ + n0 + wc);
            pw1 = *(const float4*)(We + (size_t)(k0n + wr + 16) * H_ + n0 + wc);
        }
        #pragma unroll
        for (int kk = 0; kk < TK; kk++) {
            float4 a = *(const float4*)&As[cur][kk][tr << 2];
            float4 b = *(const float4*)&Ws[cur][kk][tc << 2];
            #pragma unroll
            for (int i = 0; i < 4; i++) {
                float av = (i == 0) ? a.x : (i == 1) ? a.y : (i == 2) ? a.z : a.w;
                acc[i][0] = fmaf(av, b.x, acc[i][0]);
                acc[i][1] = fmaf(av, b.y, acc[i][1]);
                acc[i][2] = fmaf(av, b.z, acc[i][2]);
                acc[i][3] = fmaf(av, b.w, acc[i][3]);
            }
        }
        if (tile + 1 < 4) {
            As[nxt][akq + 0][arow] = pa0.x + pc0.x + pb.x;
            As[nxt][akq + 1][arow] = pa0.y + pc0.y + pb.y;
            As[nxt][akq + 2][arow] = pa0.z + pc0.z + pb.z;
            As[nxt][akq + 3][arow] = pa0.w + pc0.w + pb.w;
            As[nxt][akq + 0][arow + 32] = pa1.x + pc1.x + pb.x;
            As[nxt][akq + 1][arow + 32] = pa1.y + pc1.y + pb.y;
            As[nxt][akq + 2][arow + 32] = pa1.z + pc1.z + pb.z;
            As[nxt][akq + 3][arow + 32] = pa1.w + pc1.w + pb.w;
            *(float4*)&Ws[nxt][wr][wc]      = pw0;
            *(float4*)&Ws[nxt][wr + 16][wc] = pw1;
        }
        __syncthreads();
    }

    #pragma unroll
    for (int i = 0; i < 4; i++) {
        int row = (tr << 2) + i;
        float4 v = make_float4(acc[i][0], acc[i][1], acc[i][2], acc[i][3]);
        *(float4*)(out + row * H_ + n0 + (tc << 2)) = v;
    }
}

// ---------------------------------------------------------------------------
// Kernel 2b: gates precompute — sums split-K partial pairs.
// ---------------------------------------------------------------------------
__device__ __forceinline__ float sigmoidf_(float z) {
    return 1.0f / (1.0f + expf(-z));
}

__global__ __launch_bounds__(256, 8) void gates_kernel(
    const float* __restrict__ n_prev,
    const float* __restrict__ bi, const float* __restrict__ bf,
    const float* __restrict__ bo, const float* __restrict__ bk,
    const float* __restrict__ bv, const float* __restrict__ bq,
    const float* __restrict__ be, float* __restrict__ out_n)
{
    const int br = blockIdx.x * 256 + threadIdx.x;
    const int r = br & (H_ - 1);

    const float it = sigmoidf_(g_s2[0][br] + g_s2[1][br] + g_s2[2][br] + g_s2[3][br] + bi[r]);
    const float ft = sigmoidf_(g_s2[4][br] + g_s2[5][br] + g_s2[6][br] + g_s2[7][br] + bf[r]);
    const float ot = sigmoidf_(g_s2[8][br] + g_s2[9][br] + g_s2[10][br] + g_s2[11][br] + bo[r]);
    const float vt = g_s2[14][br] + g_s2[15][br] + bv[r];

    float e = be[r];
    #pragma unroll
    for (int p = 0; p < 8; p++) e += g_ep[p][br];
    const float nt = fmaf(ft, n_prev[br], it * expf(e));

    out_n[br] = nt;
    g_gate[br] = make_float4(ft, it * vt, ot, nt);
    g_kb[br] = g_s2[12][br] + g_s2[13][br] + bk[r];
    g_qb[br] = g_s2[16][br] + g_s2[17][br] + bq[r];
}

// ---------------------------------------------------------------------------
// Kernel 3: C-stream update v3b (R11/R14-validated, 86.3us)
// ---------------------------------------------------------------------------
__global__ __launch_bounds__(256, 4) void update3_kernel(
    const float* __restrict__ C_prev,
    float* __restrict__ out_h, float* __restrict__ out_C)
{
    __shared__ __align__(16) float ks[H_];
    __shared__ __align__(16) float qs[H_];

    const int b    = blockIdx.y;
    const int tid  = threadIdx.x;
    const int wid  = tid >> 5;
    const int lane = tid & 31;

    {
        const int c = tid << 2;
        *(float4*)&ks[c] = *(const float4*)(&g_kb[b * H_] + c);
        *(float4*)&qs[c] = *(const float4*)(&g_qb[b * H_] + c);
    }
    __syncthreads();

    const int r0 = blockIdx.x * 16 + wid * 2;
    const int br0 = b * H_ + r0;
    const float4 g0 = g_gate[br0];
    const float4 g1 = g_gate[br0 + 1];
    const size_t base0 = (size_t)b * H_ * H_ + (size_t)r0 * H_;
    const size_t base1 = base0 + H_;

    float dA0 = 0.f, dB0 = 0.f, dA1 = 0.f, dB1 = 0.f;

    #pragma unroll 2
    for (int j = 0; j < 8; j++) {
        const int c = (lane << 2) + (j << 7);
        const float4 kv = *(const float4*)&ks[c];
        float4 cp0 = __ldcs((const float4*)(C_prev + base0 + c));
        float4 cp1 = __ldcs((const float4*)(C_prev + base1 + c));

        float4 ct0, ct1;
        ct0.x = fmaf(g0.x, cp0.x, g0.y * kv.x);
        ct0.y = fmaf(g0.x, cp0.y, g0.y * kv.y);
        ct0.z = fmaf(g0.x, cp0.z, g0.y * kv.z);
        ct0.w = fmaf(g0.x, cp0.w, g0.y * kv.w);
        ct1.x = fmaf(g1.x, cp1.x, g1.y * kv.x);
        ct1.y = fmaf(g1.x, cp1.y, g1.y * kv.y);
        ct1.z = fmaf(g1.x, cp1.z, g1.y * kv.z);
        ct1.w = fmaf(g1.x, cp1.w, g1.y * kv.w);
        __stcs((float4*)(out_C + base0 + c), ct0);
        __stcs((float4*)(out_C + base1 + c), ct1);

        const float4 qv = *(const float4*)&qs[c];
        dA0 = fmaf(ct0.x, qv.x, dA0);  dB0 = fmaf(ct0.y, qv.y, dB0);
        dA0 = fmaf(ct0.z, qv.z, dA0);  dB0 = fmaf(ct0.w, qv.w, dB0);
        dA1 = fmaf(ct1.x, qv.x, dA1);  dB1 = fmaf(ct1.y, qv.y, dB1);
        dA1 = fmaf(ct1.z, qv.z, dA1);  dB1 = fmaf(ct1.w, qv.w, dB1);
    }

    float dot0 = dA0 + dB0;
    float dot1 = dA1 + dB1;
    #pragma unroll
    for (int off = 16; off; off >>= 1) {
        dot0 += __shfl_xor_sync(0xffffffffu, dot0, off);
        dot1 += __shfl_xor_sync(0xffffffffu, dot1, off);
    }

    if (lane == 0) {
        out_h[br0]     = g0.z * dot0 / g0.w;
        out_h[br0 + 1] = g1.z * dot1 / g1.w;
    }
}

// ---------------------------------------------------------------------------
extern "C" void kernel_launch(void* const* d_in, const int* in_sizes, int n_in,
                              void* d_out, int out_size)
{
    const float* x      = (const float*)d_in[0];
    const float* h_prev = (const float*)d_in[1];
    const float* C_prev = (const float*)d_in[2];
    const float* n_prev = (const float*)d_in[3];
    const float* Wi = (const float*)d_in[4];
    const float* bi = (const float*)d_in[5];
    const float* Wf = (const float*)d_in[6];
    const float* bf = (const float*)d_in[7];
    const float* Wo = (const float*)d_in[8];
    const float* bo = (const float*)d_in[9];
    const float* Wk = (const float*)d_in[10];
    const float* bk = (const float*)d_in[11];
    const float* Wv = (const float*)d_in[12];
    const float* bv = (const float*)d_in[13];
    const float* Wq = (const float*)d_in[14];
    const float* bq = (const float*)d_in[15];
    const float* We = (const float*)d_in[16];
    const float* be = (const float*)d_in[17];

    float* out_h = (float*)d_out;
    float* out_C = out_h + B_ * H_;
    float* out_n = out_C + (size_t)B_ * H_ * H_;

    static int smem_set = 0;
    if (!smem_set) {
        cudaFuncSetAttribute(mma_kernel, cudaFuncAttributeMaxDynamicSharedMemorySize,
                             SMEM_TOTAL);
        smem_set = 1;
    }

    mma_kernel<<<dim3(16, 18), 256, SMEM_TOTAL>>>(x, h_prev, Wi, Wf, Wo, Wk, Wv, Wq);
    egemm_kernel<<<dim3(16, 8), 256>>>(We, bk);
    gates_kernel<<<256, 256>>>(n_prev, bi, bf, bo, bk, bv, bq, be, out_n);
    update3_kernel<<<dim3(64, 64), 256>>>(C_prev, out_h, out_C);
}